// round 1
// baseline (speedup 1.0000x reference)
#include <cuda_runtime.h>
#include <math.h>

#define NPT 2048   // samples per trajectory (T*B = 64*32)
#define NTOT 4096  // both trajectories

// ---------------- scratch (device globals; no allocation) ----------------
__device__ float g_A[(size_t)NTOT * 10816];  // ping buffer (max stage size 16*26*26)
__device__ float g_B[(size_t)NTOT * 10816];  // pong buffer
__device__ float g_xf[(size_t)NTOT * 784];   // conv4 output, flattened [c*49+p]
__device__ float g_cm[(size_t)NTOT * 49];    // channel-summed conv4 maps
__device__ float g_r[NTOT];                  // per-frame reward

__device__ __forceinline__ float lrelu(float v) { return v >= 0.f ? v : 0.01f * v; }

#define FMA16(xc, wp, acc) do { \
  float4 q0=(wp)[0], q1=(wp)[1], q2=(wp)[2], q3=(wp)[3]; \
  acc[0]+=(xc)*q0.x; acc[1]+=(xc)*q0.y; acc[2]+=(xc)*q0.z; acc[3]+=(xc)*q0.w; \
  acc[4]+=(xc)*q1.x; acc[5]+=(xc)*q1.y; acc[6]+=(xc)*q1.z; acc[7]+=(xc)*q1.w; \
  acc[8]+=(xc)*q2.x; acc[9]+=(xc)*q2.y; acc[10]+=(xc)*q2.z; acc[11]+=(xc)*q2.w; \
  acc[12]+=(xc)*q3.x; acc[13]+=(xc)*q3.y; acc[14]+=(xc)*q3.z; acc[15]+=(xc)*q3.w; \
} while (0)

// ---------------- conv1: 84x84x4 NHWC -> 16x26x26, 7x7 stride 3, leaky ----------------
__global__ __launch_bounds__(512) void k_conv1(const float* __restrict__ ti,
                                               const float* __restrict__ tj,
                                               const float* __restrict__ w,
                                               const float* __restrict__ b) {
  extern __shared__ float sm[];
  float4* sx = (float4*)sm;            // 7056 float4 (84x84 pixels, 4 ch each)
  float* sw = sm + 7056 * 4;           // 3136: layout [(kh*7+kw)*4+ci][co]
  float* sb = sw + 3136;               // 16
  int n = blockIdx.x, tid = threadIdx.x;
  const float* x = (n < NPT) ? ti + (size_t)n * 28224 : tj + (size_t)(n - NPT) * 28224;
  const float4* xg = (const float4*)x;
  for (int i = tid; i < 7056; i += 512) sx[i] = xg[i];
  for (int i = tid; i < 3136; i += 512) {
    int co = i & 15, r = i >> 4, ci = r & 3, kk = r >> 2;
    sw[i] = w[co * 196 + ci * 49 + kk];
  }
  if (tid < 16) sb[tid] = b[tid];
  __syncthreads();
  for (int p = tid; p < 676; p += 512) {
    int oh = p / 26, ow = p - oh * 26;
    float acc[16];
#pragma unroll
    for (int i = 0; i < 16; i++) acc[i] = 0.f;
    for (int kh = 0; kh < 7; kh++) {
      const float4* xr = sx + (oh * 3 + kh) * 84 + ow * 3;
#pragma unroll
      for (int kw = 0; kw < 7; kw++) {
        float4 xv = xr[kw];
        const float4* wp = (const float4*)(sw + ((kh * 7 + kw) * 4) * 16);
        float xa[4] = {xv.x, xv.y, xv.z, xv.w};
#pragma unroll
        for (int ci = 0; ci < 4; ci++) {
          float xc = xa[ci];
          const float4* wq = wp + ci * 4;
          FMA16(xc, wq, acc);
        }
      }
    }
    float* op = g_A + (size_t)n * 10816 + p;
#pragma unroll
    for (int co = 0; co < 16; co++) op[co * 676] = lrelu(acc[co] + sb[co]);
  }
}

// ---------------- gaze matmul @26: out[c,h,k] = sum_w a[c,h,w]*(g[w,k]-.3)/(.7*.3) ----------------
__global__ __launch_bounds__(512) void k_gaze26(const float* __restrict__ gi,
                                                const float* __restrict__ gj) {
  extern __shared__ float sm[];
  float* sa = sm;            // 10816
  float* sk = sm + 10816;    // 26*28 (padded rows)
  int n = blockIdx.x, tid = threadIdx.x;
  const float* g = (n < NPT) ? gi + (size_t)n * 676 : gj + (size_t)(n - NPT) * 676;
  const float4* ag = (const float4*)(g_A + (size_t)n * 10816);
  float4* sa4 = (float4*)sa;
  for (int i = tid; i < 2704; i += 512) sa4[i] = ag[i];
  const float sc = 1.0f / (0.7f * 0.3f);
  for (int i = tid; i < 26 * 28; i += 512) {
    int wdx = i / 28, k = i - wdx * 28;
    sk[i] = (k < 26) ? (g[wdx * 26 + k] - 0.3f) * sc : 0.f;
  }
  __syncthreads();
  if (tid < 416) {
    int c = tid / 26, h = tid - c * 26;
    float acc[28];
#pragma unroll
    for (int i = 0; i < 28; i++) acc[i] = 0.f;
    const float* ar = sa + c * 676 + h * 26;
    for (int wdx = 0; wdx < 26; wdx++) {
      float xa = ar[wdx];
      const float4* kr = (const float4*)(sk + wdx * 28);
#pragma unroll
      for (int q = 0; q < 7; q++) {
        float4 kv = kr[q];
        acc[q * 4 + 0] += xa * kv.x; acc[q * 4 + 1] += xa * kv.y;
        acc[q * 4 + 2] += xa * kv.z; acc[q * 4 + 3] += xa * kv.w;
      }
    }
    float* op = g_B + (size_t)n * 10816 + c * 676 + h * 26;
    for (int k = 0; k < 26; k++) op[k] = acc[k];
  }
}

// ---------------- conv2: 16x26x26 -> 16x11x11, 5x5 stride 2, leaky ----------------
__global__ __launch_bounds__(128) void k_conv2(const float* __restrict__ w,
                                               const float* __restrict__ b) {
  extern __shared__ float sm[];
  float* si = sm;               // 10816
  float* sw = sm + 10816;       // 6400: [(ci*25+kh*5+kw)][co]
  float* sb = sw + 6400;
  int n = blockIdx.x, tid = threadIdx.x;
  const float4* ig = (const float4*)(g_B + (size_t)n * 10816);
  float4* s4 = (float4*)si;
  for (int i = tid; i < 2704; i += 128) s4[i] = ig[i];
  for (int i = tid; i < 6400; i += 128) sw[i] = w[(i & 15) * 400 + (i >> 4)];
  if (tid < 16) sb[tid] = b[tid];
  __syncthreads();
  if (tid < 121) {
    int oh = tid / 11, ow = tid - oh * 11;
    int ih0 = oh * 2, iw0 = ow * 2;
    float acc[16];
#pragma unroll
    for (int i = 0; i < 16; i++) acc[i] = 0.f;
    for (int ci = 0; ci < 16; ci++) {
      const float* irow = si + ci * 676;
#pragma unroll
      for (int kh = 0; kh < 5; kh++) {
        const float* ir = irow + (ih0 + kh) * 26 + iw0;
#pragma unroll
        for (int kw = 0; kw < 5; kw++) {
          float xc = ir[kw];
          const float4* wp = (const float4*)(sw + (ci * 25 + kh * 5 + kw) * 16);
          FMA16(xc, wp, acc);
        }
      }
    }
    float* op = g_A + (size_t)n * 1936 + tid;
#pragma unroll
    for (int co = 0; co < 16; co++) op[co * 121] = lrelu(acc[co] + sb[co]);
  }
}

// ---------------- gaze matmul @11 ----------------
__global__ __launch_bounds__(192) void k_gaze11(const float* __restrict__ gi,
                                                const float* __restrict__ gj) {
  extern __shared__ float sm[];
  float* sa = sm;            // 1936
  float* sk = sm + 1936;     // 11*12
  int n = blockIdx.x, tid = threadIdx.x;
  const float* g = (n < NPT) ? gi + (size_t)n * 121 : gj + (size_t)(n - NPT) * 121;
  const float4* ag = (const float4*)(g_A + (size_t)n * 1936);
  float4* sa4 = (float4*)sa;
  for (int i = tid; i < 484; i += 192) sa4[i] = ag[i];
  const float sc = 1.0f / (0.7f * 0.3f);
  for (int i = tid; i < 132; i += 192) {
    int wdx = i / 12, k = i - wdx * 12;
    sk[i] = (k < 11) ? (g[wdx * 11 + k] - 0.3f) * sc : 0.f;
  }
  __syncthreads();
  if (tid < 176) {
    int c = tid / 11, h = tid - c * 11;
    float acc[12];
#pragma unroll
    for (int i = 0; i < 12; i++) acc[i] = 0.f;
    const float* ar = sa + c * 121 + h * 11;
    for (int wdx = 0; wdx < 11; wdx++) {
      float xa = ar[wdx];
      const float4* kr = (const float4*)(sk + wdx * 12);
#pragma unroll
      for (int q = 0; q < 3; q++) {
        float4 kv = kr[q];
        acc[q * 4 + 0] += xa * kv.x; acc[q * 4 + 1] += xa * kv.y;
        acc[q * 4 + 2] += xa * kv.z; acc[q * 4 + 3] += xa * kv.w;
      }
    }
    float* op = g_B + (size_t)n * 1936 + c * 121 + h * 11;
    for (int k = 0; k < 11; k++) op[k] = acc[k];
  }
}

// ---------------- conv3: 16x11x11 -> 16x9x9, 3x3, leaky ----------------
__global__ __launch_bounds__(128) void k_conv3(const float* __restrict__ w,
                                               const float* __restrict__ b) {
  extern __shared__ float sm[];
  float* si = sm;               // 1936
  float* sw = sm + 1936;        // 2304
  float* sb = sw + 2304;
  int n = blockIdx.x, tid = threadIdx.x;
  const float4* ig = (const float4*)(g_B + (size_t)n * 1936);
  float4* s4 = (float4*)si;
  for (int i = tid; i < 484; i += 128) s4[i] = ig[i];
  for (int i = tid; i < 2304; i += 128) sw[i] = w[(i & 15) * 144 + (i >> 4)];
  if (tid < 16) sb[tid] = b[tid];
  __syncthreads();
  if (tid < 81) {
    int oh = tid / 9, ow = tid - oh * 9;
    float acc[16];
#pragma unroll
    for (int i = 0; i < 16; i++) acc[i] = 0.f;
    for (int ci = 0; ci < 16; ci++) {
      const float* irow = si + ci * 121;
#pragma unroll
      for (int kh = 0; kh < 3; kh++) {
        const float* ir = irow + (oh + kh) * 11 + ow;
#pragma unroll
        for (int kw = 0; kw < 3; kw++) {
          float xc = ir[kw];
          const float4* wp = (const float4*)(sw + (ci * 9 + kh * 3 + kw) * 16);
          FMA16(xc, wp, acc);
        }
      }
    }
    float* op = g_A + (size_t)n * 1296 + tid;
#pragma unroll
    for (int co = 0; co < 16; co++) op[co * 81] = lrelu(acc[co] + sb[co]);
  }
}

// ---------------- conv4: 16x9x9 -> 16x7x7, 3x3, leaky; emit xf + channel-sum cm ----------------
__global__ __launch_bounds__(128) void k_conv4(const float* __restrict__ w,
                                               const float* __restrict__ b) {
  extern __shared__ float sm[];
  float* si = sm;               // 1296
  float* sw = sm + 1296;        // 2304
  float* sb = sw + 2304;
  int n = blockIdx.x, tid = threadIdx.x;
  const float4* ig = (const float4*)(g_A + (size_t)n * 1296);
  float4* s4 = (float4*)si;
  for (int i = tid; i < 324; i += 128) s4[i] = ig[i];
  for (int i = tid; i < 2304; i += 128) sw[i] = w[(i & 15) * 144 + (i >> 4)];
  if (tid < 16) sb[tid] = b[tid];
  __syncthreads();
  if (tid < 49) {
    int oh = tid / 7, ow = tid - oh * 7;
    float acc[16];
#pragma unroll
    for (int i = 0; i < 16; i++) acc[i] = 0.f;
    for (int ci = 0; ci < 16; ci++) {
      const float* irow = si + ci * 81;
#pragma unroll
      for (int kh = 0; kh < 3; kh++) {
        const float* ir = irow + (oh + kh) * 9 + ow;
#pragma unroll
        for (int kw = 0; kw < 3; kw++) {
          float xc = ir[kw];
          const float4* wp = (const float4*)(sw + (ci * 9 + kh * 3 + kw) * 16);
          FMA16(xc, wp, acc);
        }
      }
    }
    float csum = 0.f;
    float* xp = g_xf + (size_t)n * 784 + tid;
#pragma unroll
    for (int co = 0; co < 16; co++) {
      float v = lrelu(acc[co] + sb[co]);
      xp[co * 49] = v;
      csum += v;
    }
    g_cm[(size_t)n * 49 + tid] = csum;
  }
}

// ---------------- fc: h = leaky(xf @ fc1_w^T + b1); r = h @ fc2_w^T + b2 ----------------
// Tiled: one block = 64 samples x 64 outputs, k-chunks of 16.
__global__ __launch_bounds__(256) void k_fc(const float* __restrict__ w1,
                                            const float* __restrict__ b1,
                                            const float* __restrict__ w2,
                                            const float* __restrict__ b2) {
  __shared__ float As[64][17];
  __shared__ float Bs[16][68];
  __shared__ float prs[16][64];
  int tid = threadIdx.x;
  int s0 = blockIdx.x * 64;
  int sg = tid >> 4, jg = tid & 15;
  float acc[4][4];
#pragma unroll
  for (int i = 0; i < 4; i++)
#pragma unroll
    for (int u = 0; u < 4; u++) acc[i][u] = 0.f;
  for (int k0 = 0; k0 < 784; k0 += 16) {
    for (int i = tid; i < 1024; i += 256) {
      int s = i >> 4, kk = i & 15;
      As[s][kk] = g_xf[(size_t)(s0 + s) * 784 + k0 + kk];
    }
    for (int i = tid; i < 1024; i += 256) {
      int j = i >> 4, kk = i & 15;
      Bs[kk][j] = w1[j * 784 + k0 + kk];
    }
    __syncthreads();
#pragma unroll
    for (int kk = 0; kk < 16; kk++) {
      float av[4], bv[4];
#pragma unroll
      for (int i = 0; i < 4; i++) av[i] = As[sg * 4 + i][kk];
#pragma unroll
      for (int u = 0; u < 4; u++) bv[u] = Bs[kk][jg * 4 + u];
#pragma unroll
      for (int i = 0; i < 4; i++)
#pragma unroll
        for (int u = 0; u < 4; u++) acc[i][u] += av[i] * bv[u];
    }
    __syncthreads();
  }
  // epilogue: leaky + fc2 contraction, deterministic smem reduction
#pragma unroll
  for (int i = 0; i < 4; i++) {
    float pr = 0.f;
#pragma unroll
    for (int u = 0; u < 4; u++) {
      int j = jg * 4 + u;
      float h = acc[i][u] + b1[j];
      h = lrelu(h);
      pr += h * w2[j];
    }
    prs[jg][sg * 4 + i] = pr;
  }
  __syncthreads();
  if (tid < 64) {
    float s = 0.f;
#pragma unroll
    for (int j = 0; j < 16; j++) s += prs[j][tid];
    g_r[s0 + tid] = s + b2[0];
  }
}

// ---------------- reduce r: logits[64] + abs[32] ----------------
__global__ void k_reduce_r(float* __restrict__ out) {
  __shared__ float sab[64];
  int tid = threadIdx.x;  // 64 threads
  int traj = tid >> 5, b = tid & 31;
  float s = 0.f, sa = 0.f;
  for (int t = 0; t < 64; t++) {
    float r = g_r[traj * 2048 + t * 32 + b];
    s += r;
    sa += fabsf(r);
  }
  out[tid] = s;           // logits: [cum_i(32), cum_j(32)]
  sab[tid] = sa;
  __syncthreads();
  if (tid < 32) out[64 + tid] = sab[tid] + sab[32 + tid];
}

// ---------------- cm normalize: per (traj, t) min/max over B*7*7 ----------------
__global__ __launch_bounds__(256) void k_cmnorm(float* __restrict__ out) {
  __shared__ float sv[1568];
  __shared__ float smn[8], smx[8];
  __shared__ float fmn, fmx;
  int idx = blockIdx.x;
  int traj = idx >> 6, t = idx & 63;
  int tid = threadIdx.x;
  const float* base = g_cm + ((size_t)(traj * 2048 + t * 32)) * 49;
  float mn = 1e30f, mx = -1e30f;
  for (int i = tid; i < 1568; i += 256) {
    float v = base[i];
    sv[i] = v;
    mn = fminf(mn, v);
    mx = fmaxf(mx, v);
  }
#pragma unroll
  for (int o = 16; o; o >>= 1) {
    mn = fminf(mn, __shfl_xor_sync(0xffffffffu, mn, o));
    mx = fmaxf(mx, __shfl_xor_sync(0xffffffffu, mx, o));
  }
  if ((tid & 31) == 0) { smn[tid >> 5] = mn; smx[tid >> 5] = mx; }
  __syncthreads();
  if (tid == 0) {
    float a = smn[0], bb = smx[0];
    for (int i = 1; i < 8; i++) { a = fminf(a, smn[i]); bb = fmaxf(bb, smx[i]); }
    fmn = a; fmx = bb;
  }
  __syncthreads();
  float m = fmn, inv = 1.f / (fmx - m);
  float* o = out + 96 + (size_t)traj * 100352 + (size_t)t * 1568;
  for (int i = tid; i < 1568; i += 256) o[i] = (sv[i] - m) * inv;
}

// ---------------- launch ----------------
extern "C" void kernel_launch(void* const* d_in, const int* in_sizes, int n_in,
                              void* d_out, int out_size) {
  const float* ti   = (const float*)d_in[0];
  const float* tj   = (const float*)d_in[1];
  const float* g26i = (const float*)d_in[2];
  const float* g11i = (const float*)d_in[3];
  const float* g26j = (const float*)d_in[4];
  const float* g11j = (const float*)d_in[5];
  const float* w1 = (const float*)d_in[6];  const float* b1 = (const float*)d_in[7];
  const float* w2 = (const float*)d_in[8];  const float* b2 = (const float*)d_in[9];
  const float* w3 = (const float*)d_in[10]; const float* b3 = (const float*)d_in[11];
  const float* w4 = (const float*)d_in[12]; const float* b4 = (const float*)d_in[13];
  const float* f1w = (const float*)d_in[14]; const float* f1b = (const float*)d_in[15];
  const float* f2w = (const float*)d_in[16]; const float* f2b = (const float*)d_in[17];
  float* out = (float*)d_out;

  cudaFuncSetAttribute(k_conv1, cudaFuncAttributeMaxDynamicSharedMemorySize, 126976);
  cudaFuncSetAttribute(k_conv2, cudaFuncAttributeMaxDynamicSharedMemorySize, 70656);

  k_conv1<<<NTOT, 512, 125504>>>(ti, tj, w1, b1);
  k_gaze26<<<NTOT, 512, 46176>>>(g26i, g26j);
  k_conv2<<<NTOT, 128, 68928>>>(w2, b2);
  k_gaze11<<<NTOT, 192, 8272>>>(g11i, g11j);
  k_conv3<<<NTOT, 128, 17024>>>(w3, b3);
  k_conv4<<<NTOT, 128, 14464>>>(w4, b4);
  k_fc<<<NTOT / 64, 256>>>(f1w, f1b, f2w, f2b);
  k_reduce_r<<<1, 64>>>(out);
  k_cmnorm<<<128, 256>>>(out);
}

// round 2
// speedup vs baseline: 1.1110x; 1.1110x over previous
#include <cuda_runtime.h>
#include <math.h>

#define NPT 2048   // samples per trajectory (T*B = 64*32)
#define NTOT 4096  // both trajectories
typedef unsigned long long ull;

// ---------------- scratch (device globals; no allocation) ----------------
__device__ float g_xf[(size_t)NTOT * 784];   // conv4 output, flattened [c*49+p]
__device__ float g_cm[(size_t)NTOT * 49];    // channel-summed conv4 maps
__device__ float g_r[NTOT];                  // per-frame reward

__device__ __forceinline__ float lrelu(float v) { return v >= 0.f ? v : 0.01f * v; }
__device__ __forceinline__ ull pack2(float x, float y) {
  ull r; asm("mov.b64 %0,{%1,%2};" : "=l"(r) : "f"(x), "f"(y)); return r;
}
__device__ __forceinline__ void ffma2(ull& d, ull a, ull b) {
  asm("fma.rn.f32x2 %0,%1,%2,%0;" : "+l"(d) : "l"(a), "l"(b));
}
__device__ __forceinline__ float2 unpack2(ull v) {
  float2 r; asm("mov.b64 {%0,%1},%2;" : "=f"(r.x), "=f"(r.y) : "l"(v)); return r;
}

// smem float offsets (phase B reuses the conv1 input region [0, 28224))
#define OFF_W2T   0       // 6400
#define OFF_SB2   6400    // 16
#define OFF_K11   6416    // 132 (11 rows x 12 padded)
#define OFF_ACT11 6560    // 1936
#define OFF_W3T   8496    // 2304
#define OFF_SB3   10800   // 16
#define OFF_ACT9  10816   // 1296
#define OFF_W4T   12112   // 2304
#define OFF_SB4   14416   // 16
#define OFF_SCM   14432   // 98
#define OFF_SACT  28224   // 10816 (conv1 out / gaze26 in-place)
#define OFF_SW1   39040   // 3136
#define OFF_SB1   42176   // 16
#define OFF_SK26  42192   // 728 (26 rows x 28 padded)
#define SMEM_FLOATS 42920 // * 4 = 171680 bytes

// ============ fused per-sample net: conv1..conv4 (+gaze) ============
__global__ __launch_bounds__(512, 1) void k_net(
    const float* __restrict__ ti, const float* __restrict__ tj,
    const float* __restrict__ g26i, const float* __restrict__ g26j,
    const float* __restrict__ g11i, const float* __restrict__ g11j,
    const float* __restrict__ w1, const float* __restrict__ b1,
    const float* __restrict__ w2, const float* __restrict__ b2,
    const float* __restrict__ w3, const float* __restrict__ b3,
    const float* __restrict__ w4, const float* __restrict__ b4) {
  extern __shared__ float sm[];
  int n = blockIdx.x, tid = threadIdx.x;
  const float sc = 1.0f / (0.7f * 0.3f);

  const float* x   = (n < NPT) ? ti   + (size_t)n * 28224 : tj   + (size_t)(n - NPT) * 28224;
  const float* g26 = (n < NPT) ? g26i + (size_t)n * 676   : g26j + (size_t)(n - NPT) * 676;
  const float* g11 = (n < NPT) ? g11i + (size_t)n * 121   : g11j + (size_t)(n - NPT) * 121;

  float* sact = sm + OFF_SACT;
  float* sw1  = sm + OFF_SW1;
  float* sb1  = sm + OFF_SB1;
  float* sK26 = sm + OFF_SK26;

  // ---- phase 1: load input (as float4), conv1 weights, gaze26 K ----
  {
    const float4* xg = (const float4*)x;
    float4* sx4 = (float4*)sm;
    for (int i = tid; i < 7056; i += 512) sx4[i] = xg[i];
    for (int i = tid; i < 3136; i += 512) {
      int co = i & 15, r = i >> 4, ci = r & 3, kk = r >> 2;
      sw1[i] = w1[co * 196 + ci * 49 + kk];   // layout [(kk*4+ci)*16 + co]
    }
    if (tid < 16) sb1[tid] = b1[tid];
    for (int i = tid; i < 728; i += 512) {
      int wdx = i / 28, k = i - wdx * 28;
      sK26[i] = (k < 26) ? (g26[wdx * 26 + k] - 0.3f) * sc : 0.f;
    }
  }
  __syncthreads();

  // ---- phase 2: conv1 7x7 s3, 4->16, leaky -> sact[co*676+p] ----
  for (int p = tid; p < 676; p += 512) {
    int oh = p / 26, ow = p - oh * 26;
    ull acc[8];
#pragma unroll
    for (int q = 0; q < 8; q++) acc[q] = 0ULL;
    for (int kh = 0; kh < 7; kh++) {
      const float4* xr = ((const float4*)sm) + (oh * 3 + kh) * 84 + ow * 3;
#pragma unroll
      for (int kw = 0; kw < 7; kw++) {
        float4 xv = xr[kw];
        const ulonglong2* wq = (const ulonglong2*)(sw1 + (kh * 7 + kw) * 64);
        float xa[4] = {xv.x, xv.y, xv.z, xv.w};
#pragma unroll
        for (int ci = 0; ci < 4; ci++) {
          ull xx = pack2(xa[ci], xa[ci]);
          ulonglong2 a0 = wq[ci * 2], a1 = wq[ci * 2 + 1];
          ffma2(acc[0], xx, a0.x); ffma2(acc[1], xx, a0.y);
          ffma2(acc[2], xx, a1.x); ffma2(acc[3], xx, a1.y);
          // wait: 16 co = 8 ull = 4 ulonglong2; indices ci*4..ci*4+3
        }
      }
    }
    // epilogue handled below (recompute with correct weight indexing)
    (void)acc;
    // NOTE: real computation below
    ull ac[8];
#pragma unroll
    for (int q = 0; q < 8; q++) ac[q] = 0ULL;
    for (int kh = 0; kh < 7; kh++) {
      const float4* xr = ((const float4*)sm) + (oh * 3 + kh) * 84 + ow * 3;
#pragma unroll
      for (int kw = 0; kw < 7; kw++) {
        float4 xv = xr[kw];
        const ulonglong2* wq = (const ulonglong2*)(sw1 + (kh * 7 + kw) * 64);
        float xa[4] = {xv.x, xv.y, xv.z, xv.w};
#pragma unroll
        for (int ci = 0; ci < 4; ci++) {
          ull xx = pack2(xa[ci], xa[ci]);
          ulonglong2 a0 = wq[ci * 4 + 0], a1 = wq[ci * 4 + 1];
          ulonglong2 a2 = wq[ci * 4 + 2], a3 = wq[ci * 4 + 3];
          ffma2(ac[0], xx, a0.x); ffma2(ac[1], xx, a0.y);
          ffma2(ac[2], xx, a1.x); ffma2(ac[3], xx, a1.y);
          ffma2(ac[4], xx, a2.x); ffma2(ac[5], xx, a2.y);
          ffma2(ac[6], xx, a3.x); ffma2(ac[7], xx, a3.y);
        }
      }
    }
#pragma unroll
    for (int q = 0; q < 8; q++) {
      float2 v = unpack2(ac[q]);
      int co = q * 2;
      sact[co * 676 + p]       = lrelu(v.x + sb1[co]);
      sact[(co + 1) * 676 + p] = lrelu(v.y + sb1[co + 1]);
    }
  }
  __syncthreads();

  // ---- phase 3: load phase-B weights into freed input region; gaze26 in-place ----
  {
    float* w2t = sm + OFF_W2T;
    for (int i = tid; i < 6400; i += 512) w2t[i] = w2[(i & 15) * 400 + (i >> 4)];
    if (tid < 16) sm[OFF_SB2 + tid] = b2[tid];
    for (int i = tid; i < 132; i += 512) {
      int wdx = i / 12, k = i - wdx * 12;
      sm[OFF_K11 + i] = (k < 11) ? (g11[wdx * 11 + k] - 0.3f) * sc : 0.f;
    }
    float* w3t = sm + OFF_W3T;
    for (int i = tid; i < 2304; i += 512) w3t[i] = w3[(i & 15) * 144 + (i >> 4)];
    if (tid < 16) sm[OFF_SB3 + tid] = b3[tid];
    float* w4t = sm + OFF_W4T;
    for (int i = tid; i < 2304; i += 512) w4t[i] = w4[(i & 15) * 144 + (i >> 4)];
    if (tid < 16) sm[OFF_SB4 + tid] = b4[tid];
  }
  if (tid < 416) {  // gaze26: one (c,h) row per thread, in-place
    int c = tid / 26, h = tid - c * 26;
    float* row = sact + c * 676 + h * 26;
    float a[26];
#pragma unroll
    for (int w = 0; w < 26; w++) a[w] = row[w];
    ull acc[14];
#pragma unroll
    for (int q = 0; q < 14; q++) acc[q] = 0ULL;
#pragma unroll
    for (int w = 0; w < 26; w++) {
      ull xx = pack2(a[w], a[w]);
      const ulonglong2* kr = (const ulonglong2*)(sK26 + w * 28);
#pragma unroll
      for (int q = 0; q < 7; q++) {
        ulonglong2 kv = kr[q];
        ffma2(acc[2 * q], xx, kv.x);
        ffma2(acc[2 * q + 1], xx, kv.y);
      }
    }
#pragma unroll
    for (int q = 0; q < 13; q++) {
      float2 v = unpack2(acc[q]);
      row[2 * q] = v.x; row[2 * q + 1] = v.y;
    }
  }
  __syncthreads();

  // ---- phase 4: conv2 5x5 s2, 16->16, leaky -> act11[co*121+p] ----
  if (tid < 242) {
    int half = tid & 1, p = tid >> 1;
    int oh = p / 11, ow = p - oh * 11;
    int ih0 = oh * 2, iw0 = ow * 2;
    ull acc[4] = {0ULL, 0ULL, 0ULL, 0ULL};
    const float* w2t = sm + OFF_W2T;
    for (int ci = 0; ci < 16; ci++) {
      const float* irow = sact + ci * 676;
#pragma unroll
      for (int kh = 0; kh < 5; kh++) {
        const float* ir = irow + (ih0 + kh) * 26 + iw0;
#pragma unroll
        for (int kw = 0; kw < 5; kw++) {
          ull xx = pack2(ir[kw], ir[kw]);
          const ulonglong2* wq =
              (const ulonglong2*)(w2t + (ci * 25 + kh * 5 + kw) * 16 + half * 8);
          ulonglong2 a0 = wq[0], a1 = wq[1];
          ffma2(acc[0], xx, a0.x); ffma2(acc[1], xx, a0.y);
          ffma2(acc[2], xx, a1.x); ffma2(acc[3], xx, a1.y);
        }
      }
    }
    float* act11 = sm + OFF_ACT11;
    const float* sb2 = sm + OFF_SB2;
#pragma unroll
    for (int q = 0; q < 4; q++) {
      float2 v = unpack2(acc[q]);
      int co = half * 8 + q * 2;
      act11[co * 121 + p]       = lrelu(v.x + sb2[co]);
      act11[(co + 1) * 121 + p] = lrelu(v.y + sb2[co + 1]);
    }
  }
  __syncthreads();

  // ---- phase 5: gaze11 in-place on act11 ----
  if (tid < 176) {
    int c = tid / 11, h = tid - c * 11;
    float* row = sm + OFF_ACT11 + c * 121 + h * 11;
    const float* K11 = sm + OFF_K11;
    float a[11];
#pragma unroll
    for (int w = 0; w < 11; w++) a[w] = row[w];
    ull acc[6];
#pragma unroll
    for (int q = 0; q < 6; q++) acc[q] = 0ULL;
#pragma unroll
    for (int w = 0; w < 11; w++) {
      ull xx = pack2(a[w], a[w]);
      const ulonglong2* kr = (const ulonglong2*)(K11 + w * 12);
#pragma unroll
      for (int q = 0; q < 3; q++) {
        ulonglong2 kv = kr[q];
        ffma2(acc[2 * q], xx, kv.x);
        ffma2(acc[2 * q + 1], xx, kv.y);
      }
    }
#pragma unroll
    for (int q = 0; q < 5; q++) {
      float2 v = unpack2(acc[q]);
      row[2 * q] = v.x; row[2 * q + 1] = v.y;
    }
    float2 v5 = unpack2(acc[5]);
    row[10] = v5.x;
  }
  __syncthreads();

  // ---- phase 6: conv3 3x3, 16->16, leaky -> act9[co*81+p] ----
  if (tid < 162) {
    int half = tid & 1, p = tid >> 1;
    int oh = p / 9, ow = p - oh * 9;
    ull acc[4] = {0ULL, 0ULL, 0ULL, 0ULL};
    const float* w3t = sm + OFF_W3T;
    const float* act11 = sm + OFF_ACT11;
    for (int ci = 0; ci < 16; ci++) {
      const float* irow = act11 + ci * 121;
#pragma unroll
      for (int kh = 0; kh < 3; kh++) {
        const float* ir = irow + (oh + kh) * 11 + ow;
#pragma unroll
        for (int kw = 0; kw < 3; kw++) {
          ull xx = pack2(ir[kw], ir[kw]);
          const ulonglong2* wq =
              (const ulonglong2*)(w3t + (ci * 9 + kh * 3 + kw) * 16 + half * 8);
          ulonglong2 a0 = wq[0], a1 = wq[1];
          ffma2(acc[0], xx, a0.x); ffma2(acc[1], xx, a0.y);
          ffma2(acc[2], xx, a1.x); ffma2(acc[3], xx, a1.y);
        }
      }
    }
    float* act9 = sm + OFF_ACT9;
    const float* sb3 = sm + OFF_SB3;
#pragma unroll
    for (int q = 0; q < 4; q++) {
      float2 v = unpack2(acc[q]);
      int co = half * 8 + q * 2;
      act9[co * 81 + p]       = lrelu(v.x + sb3[co]);
      act9[(co + 1) * 81 + p] = lrelu(v.y + sb3[co + 1]);
    }
  }
  __syncthreads();

  // ---- phase 7: conv4 3x3, 16->16, leaky -> g_xf + channel sums ----
  if (tid < 98) {
    int half = tid & 1, p = tid >> 1;
    int oh = p / 7, ow = p - oh * 7;
    ull acc[4] = {0ULL, 0ULL, 0ULL, 0ULL};
    const float* w4t = sm + OFF_W4T;
    const float* act9 = sm + OFF_ACT9;
    for (int ci = 0; ci < 16; ci++) {
      const float* irow = act9 + ci * 81;
#pragma unroll
      for (int kh = 0; kh < 3; kh++) {
        const float* ir = irow + (oh + kh) * 9 + ow;
#pragma unroll
        for (int kw = 0; kw < 3; kw++) {
          ull xx = pack2(ir[kw], ir[kw]);
          const ulonglong2* wq =
              (const ulonglong2*)(w4t + (ci * 9 + kh * 3 + kw) * 16 + half * 8);
          ulonglong2 a0 = wq[0], a1 = wq[1];
          ffma2(acc[0], xx, a0.x); ffma2(acc[1], xx, a0.y);
          ffma2(acc[2], xx, a1.x); ffma2(acc[3], xx, a1.y);
        }
      }
    }
    const float* sb4 = sm + OFF_SB4;
    float* xp = g_xf + (size_t)n * 784 + p;
    float cs = 0.f;
#pragma unroll
    for (int q = 0; q < 4; q++) {
      float2 v = unpack2(acc[q]);
      int co = half * 8 + q * 2;
      float v0 = lrelu(v.x + sb4[co]);
      float v1 = lrelu(v.y + sb4[co + 1]);
      xp[co * 49] = v0;
      xp[(co + 1) * 49] = v1;
      cs += v0 + v1;
    }
    sm[OFF_SCM + tid] = cs;
  }
  __syncthreads();
  if (tid < 49) g_cm[(size_t)n * 49 + tid] = sm[OFF_SCM + 2 * tid] + sm[OFF_SCM + 2 * tid + 1];
}

// ---------------- fc: h = leaky(xf @ fc1_w^T + b1); r = h @ fc2_w^T + b2 ----------------
__global__ __launch_bounds__(256) void k_fc(const float* __restrict__ w1,
                                            const float* __restrict__ b1,
                                            const float* __restrict__ w2,
                                            const float* __restrict__ b2) {
  __shared__ float As[64][17];
  __shared__ float Bs[16][68];
  __shared__ float prs[16][64];
  int tid = threadIdx.x;
  int s0 = blockIdx.x * 64;
  int sg = tid >> 4, jg = tid & 15;
  float acc[4][4];
#pragma unroll
  for (int i = 0; i < 4; i++)
#pragma unroll
    for (int u = 0; u < 4; u++) acc[i][u] = 0.f;
  for (int k0 = 0; k0 < 784; k0 += 16) {
    for (int i = tid; i < 1024; i += 256) {
      int s = i >> 4, kk = i & 15;
      As[s][kk] = g_xf[(size_t)(s0 + s) * 784 + k0 + kk];
    }
    for (int i = tid; i < 1024; i += 256) {
      int j = i >> 4, kk = i & 15;
      Bs[kk][j] = w1[j * 784 + k0 + kk];
    }
    __syncthreads();
#pragma unroll
    for (int kk = 0; kk < 16; kk++) {
      float av[4], bv[4];
#pragma unroll
      for (int i = 0; i < 4; i++) av[i] = As[sg * 4 + i][kk];
#pragma unroll
      for (int u = 0; u < 4; u++) bv[u] = Bs[kk][jg * 4 + u];
#pragma unroll
      for (int i = 0; i < 4; i++)
#pragma unroll
        for (int u = 0; u < 4; u++) acc[i][u] += av[i] * bv[u];
    }
    __syncthreads();
  }
#pragma unroll
  for (int i = 0; i < 4; i++) {
    float pr = 0.f;
#pragma unroll
    for (int u = 0; u < 4; u++) {
      int j = jg * 4 + u;
      float h = acc[i][u] + b1[j];
      h = lrelu(h);
      pr += h * w2[j];
    }
    prs[jg][sg * 4 + i] = pr;
  }
  __syncthreads();
  if (tid < 64) {
    float s = 0.f;
#pragma unroll
    for (int j = 0; j < 16; j++) s += prs[j][tid];
    g_r[s0 + tid] = s + b2[0];
  }
}

// ---------------- reduce r: logits[64] + abs[32] ----------------
__global__ void k_reduce_r(float* __restrict__ out) {
  __shared__ float sab[64];
  int tid = threadIdx.x;  // 64 threads
  int traj = tid >> 5, b = tid & 31;
  float s = 0.f, sa = 0.f;
  for (int t = 0; t < 64; t++) {
    float r = g_r[traj * 2048 + t * 32 + b];
    s += r;
    sa += fabsf(r);
  }
  out[tid] = s;
  sab[tid] = sa;
  __syncthreads();
  if (tid < 32) out[64 + tid] = sab[tid] + sab[32 + tid];
}

// ---------------- cm normalize: per (traj, t) min/max over B*7*7 ----------------
__global__ __launch_bounds__(256) void k_cmnorm(float* __restrict__ out) {
  __shared__ float sv[1568];
  __shared__ float smn[8], smx[8];
  __shared__ float fmn, fmx;
  int idx = blockIdx.x;
  int traj = idx >> 6, t = idx & 63;
  int tid = threadIdx.x;
  const float* base = g_cm + ((size_t)(traj * 2048 + t * 32)) * 49;
  float mn = 1e30f, mx = -1e30f;
  for (int i = tid; i < 1568; i += 256) {
    float v = base[i];
    sv[i] = v;
    mn = fminf(mn, v);
    mx = fmaxf(mx, v);
  }
#pragma unroll
  for (int o = 16; o; o >>= 1) {
    mn = fminf(mn, __shfl_xor_sync(0xffffffffu, mn, o));
    mx = fmaxf(mx, __shfl_xor_sync(0xffffffffu, mx, o));
  }
  if ((tid & 31) == 0) { smn[tid >> 5] = mn; smx[tid >> 5] = mx; }
  __syncthreads();
  if (tid == 0) {
    float a = smn[0], bb = smx[0];
    for (int i = 1; i < 8; i++) { a = fminf(a, smn[i]); bb = fmaxf(bb, smx[i]); }
    fmn = a; fmx = bb;
  }
  __syncthreads();
  float m = fmn, inv = 1.f / (fmx - m);
  float* o = out + 96 + (size_t)traj * 100352 + (size_t)t * 1568;
  for (int i = tid; i < 1568; i += 256) o[i] = (sv[i] - m) * inv;
}

// ---------------- launch ----------------
extern "C" void kernel_launch(void* const* d_in, const int* in_sizes, int n_in,
                              void* d_out, int out_size) {
  const float* ti   = (const float*)d_in[0];
  const float* tj   = (const float*)d_in[1];
  const float* g26i = (const float*)d_in[2];
  const float* g11i = (const float*)d_in[3];
  const float* g26j = (const float*)d_in[4];
  const float* g11j = (const float*)d_in[5];
  const float* w1 = (const float*)d_in[6];  const float* b1 = (const float*)d_in[7];
  const float* w2 = (const float*)d_in[8];  const float* b2 = (const float*)d_in[9];
  const float* w3 = (const float*)d_in[10]; const float* b3 = (const float*)d_in[11];
  const float* w4 = (const float*)d_in[12]; const float* b4 = (const float*)d_in[13];
  const float* f1w = (const float*)d_in[14]; const float* f1b = (const float*)d_in[15];
  const float* f2w = (const float*)d_in[16]; const float* f2b = (const float*)d_in[17];
  float* out = (float*)d_out;

  cudaFuncSetAttribute(k_net, cudaFuncAttributeMaxDynamicSharedMemorySize,
                       SMEM_FLOATS * 4);

  k_net<<<NTOT, 512, SMEM_FLOATS * 4>>>(ti, tj, g26i, g26j, g11i, g11j,
                                        w1, b1, w2, b2, w3, b3, w4, b4);
  k_fc<<<NTOT / 64, 256>>>(f1w, f1b, f2w, f2b);
  k_reduce_r<<<1, 64>>>(out);
  k_cmnorm<<<128, 256>>>(out);
}

// round 3
// speedup vs baseline: 1.4656x; 1.3192x over previous
#include <cuda_runtime.h>
#include <math.h>

#define NPT 2048
#define NTOT 4096
typedef unsigned long long ull;

__device__ float g_xf[(size_t)NTOT * 784];
__device__ float g_cm[(size_t)NTOT * 49];
__device__ float g_r[NTOT];

__device__ __forceinline__ float lrelu(float v) { return v >= 0.f ? v : 0.01f * v; }
__device__ __forceinline__ ull pack2(float x) {
  ull r; asm("mov.b64 %0,{%1,%1};" : "=l"(r) : "f"(x)); return r;
}
__device__ __forceinline__ void ffma2(ull& d, ull a, ull b) {
  asm("fma.rn.f32x2 %0,%1,%2,%0;" : "+l"(d) : "l"(a), "l"(b));
}
__device__ __forceinline__ float2 unpack2(ull v) {
  float2 r; asm("mov.b64 {%0,%1},%2;" : "=f"(r.x), "=f"(r.y) : "l"(v)); return r;
}

// smem float offsets (total 26078 floats = 104312 B -> 2 blocks/SM)
#define OFF_ACT26 0        // 10816  [co*676 + p]
#define OFF_W2T   10816    // 6400   [(ci*25+t)*16 + co]
#define OFF_W3T   17216    // 2304
#define OFF_W4T   19520    // 2304
#define OFF_K26   21824    // 728    [w*28 + k]
#define OFF_K11   22552    // 132    [w*12 + k]
#define OFF_ACT11 22684    // 1936   [co*121 + p]   (aliases W1 region)
#define OFF_ACT9  24620    // 1296   [co*81 + p]
#define OFF_W1    22684    // 3136   [(kh*7+kw)*64 + ci*16 + co] (dead after conv1)
#define OFF_SB1   25916
#define OFF_SB2   25932
#define OFF_SB3   25948
#define OFF_SB4   25964
#define SMEM_FLOATS 25980

__global__ __launch_bounds__(256, 2) void k_net(
    const float* __restrict__ ti, const float* __restrict__ tj,
    const float* __restrict__ g26i, const float* __restrict__ g26j,
    const float* __restrict__ g11i, const float* __restrict__ g11j,
    const float* __restrict__ w1, const float* __restrict__ b1,
    const float* __restrict__ w2, const float* __restrict__ b2,
    const float* __restrict__ w3, const float* __restrict__ b3,
    const float* __restrict__ w4, const float* __restrict__ b4) {
  extern __shared__ float sm[];
  int n = blockIdx.x, tid = threadIdx.x;
  const float sc = 1.0f / (0.7f * 0.3f);

  const float* x   = (n < NPT) ? ti   + (size_t)n * 28224 : tj   + (size_t)(n - NPT) * 28224;
  const float* g26 = (n < NPT) ? g26i + (size_t)n * 676   : g26j + (size_t)(n - NPT) * 676;
  const float* g11 = (n < NPT) ? g11i + (size_t)n * 121   : g11j + (size_t)(n - NPT) * 121;

  // ---- phase 0: load ALL weights / gaze kernels ----
  for (int i = tid; i < 3136; i += 256) {
    int co = i & 15, r = i >> 4, ci = r & 3, kk = r >> 2;
    sm[OFF_W1 + i] = w1[co * 196 + ci * 49 + kk];
  }
  for (int i = tid; i < 6400; i += 256) sm[OFF_W2T + i] = w2[(i & 15) * 400 + (i >> 4)];
  for (int i = tid; i < 2304; i += 256) sm[OFF_W3T + i] = w3[(i & 15) * 144 + (i >> 4)];
  for (int i = tid; i < 2304; i += 256) sm[OFF_W4T + i] = w4[(i & 15) * 144 + (i >> 4)];
  for (int i = tid; i < 728; i += 256) {
    int wdx = i / 28, k = i - wdx * 28;
    sm[OFF_K26 + i] = (k < 26) ? (g26[wdx * 26 + k] - 0.3f) * sc : 0.f;
  }
  for (int i = tid; i < 132; i += 256) {
    int wdx = i / 12, k = i - wdx * 12;
    sm[OFF_K11 + i] = (k < 11) ? (g11[wdx * 11 + k] - 0.3f) * sc : 0.f;
  }
  if (tid < 16) {
    sm[OFF_SB1 + tid] = b1[tid]; sm[OFF_SB2 + tid] = b2[tid];
    sm[OFF_SB3 + tid] = b3[tid]; sm[OFF_SB4 + tid] = b4[tid];
  }
  __syncthreads();

  // ---- phase 1: conv1 7x7 s3 4->16, leaky. Pixel-pairs, input from global ----
  // item i in [0,338): oh=i/13, pixels (oh, 2j) and (oh, 2j+1), j=i%13
  {
    const float4* xg = (const float4*)x;
    const float* sw1 = sm + OFF_W1;
    const float* sb1 = sm + OFF_SB1;
    for (int i = tid; i < 338; i += 256) {
      int oh = i / 13, j = i - oh * 13;
      int ow0 = 2 * j;
      ull a0[8], a1[8];
#pragma unroll
      for (int q = 0; q < 8; q++) { a0[q] = 0ULL; a1[q] = 0ULL; }
      for (int kh = 0; kh < 7; kh++) {
        const float4* xr = xg + (oh * 3 + kh) * 84 + 6 * j;
        float4 xv[10];
#pragma unroll
        for (int q = 0; q < 10; q++) xv[q] = xr[q];
#pragma unroll
        for (int kw = 0; kw < 7; kw++) {
          const ulonglong2* wq = (const ulonglong2*)(sw1 + (kh * 7 + kw) * 64);
          float xa[4] = {xv[kw].x, xv[kw].y, xv[kw].z, xv[kw].w};
          float xb[4] = {xv[kw + 3].x, xv[kw + 3].y, xv[kw + 3].z, xv[kw + 3].w};
#pragma unroll
          for (int ci = 0; ci < 4; ci++) {
            ull xx0 = pack2(xa[ci]);
            ull xx1 = pack2(xb[ci]);
            ulonglong2 q0 = wq[ci * 4 + 0], q1 = wq[ci * 4 + 1];
            ulonglong2 q2 = wq[ci * 4 + 2], q3 = wq[ci * 4 + 3];
            ffma2(a0[0], xx0, q0.x); ffma2(a0[1], xx0, q0.y);
            ffma2(a0[2], xx0, q1.x); ffma2(a0[3], xx0, q1.y);
            ffma2(a0[4], xx0, q2.x); ffma2(a0[5], xx0, q2.y);
            ffma2(a0[6], xx0, q3.x); ffma2(a0[7], xx0, q3.y);
            ffma2(a1[0], xx1, q0.x); ffma2(a1[1], xx1, q0.y);
            ffma2(a1[2], xx1, q1.x); ffma2(a1[3], xx1, q1.y);
            ffma2(a1[4], xx1, q2.x); ffma2(a1[5], xx1, q2.y);
            ffma2(a1[6], xx1, q3.x); ffma2(a1[7], xx1, q3.y);
          }
        }
      }
      float* sact = sm + OFF_ACT26;
      int p0 = oh * 26 + ow0;
#pragma unroll
      for (int q = 0; q < 8; q++) {
        float2 v0 = unpack2(a0[q]);
        float2 v1 = unpack2(a1[q]);
        int co = 2 * q;
        sact[co * 676 + p0]           = lrelu(v0.x + sb1[co]);
        sact[(co + 1) * 676 + p0]     = lrelu(v0.y + sb1[co + 1]);
        sact[co * 676 + p0 + 1]       = lrelu(v1.x + sb1[co]);
        sact[(co + 1) * 676 + p0 + 1] = lrelu(v1.y + sb1[co + 1]);
      }
    }
  }
  __syncthreads();

  // ---- phase 2: gaze26 in-place (row per thread) ----
  for (int i = tid; i < 416; i += 256) {
    int c = i / 26, h = i - c * 26;
    float* row = sm + OFF_ACT26 + c * 676 + h * 26;
    const float* K = sm + OFF_K26;
    float a[26];
#pragma unroll
    for (int w = 0; w < 26; w++) a[w] = row[w];
    ull acc[14];
#pragma unroll
    for (int q = 0; q < 14; q++) acc[q] = 0ULL;
#pragma unroll
    for (int w = 0; w < 26; w++) {
      ull xx = pack2(a[w]);
      const ulonglong2* kr = (const ulonglong2*)(K + w * 28);
#pragma unroll
      for (int q = 0; q < 7; q++) {
        ulonglong2 kv = kr[q];
        ffma2(acc[2 * q], xx, kv.x);
        ffma2(acc[2 * q + 1], xx, kv.y);
      }
    }
#pragma unroll
    for (int q = 0; q < 13; q++) {
      float2 v = unpack2(acc[q]);
      row[2 * q] = v.x; row[2 * q + 1] = v.y;
    }
  }
  __syncthreads();

  // ---- phase 3: conv2 5x5 s2 16->16, leaky. 1 px x 16 co per thread ----
  if (tid < 121) {
    int oh = tid / 11, ow = tid - oh * 11;
    int ih0 = oh * 2, iw0 = ow * 2;
    ull acc[8];
#pragma unroll
    for (int q = 0; q < 8; q++) acc[q] = 0ULL;
    const float* w2t = sm + OFF_W2T;
    const float* sact = sm + OFF_ACT26;
    for (int ci = 0; ci < 16; ci++) {
      const float* irow = sact + ci * 676;
#pragma unroll
      for (int kh = 0; kh < 5; kh++) {
        const float* ir = irow + (ih0 + kh) * 26 + iw0;
#pragma unroll
        for (int kw = 0; kw < 5; kw++) {
          ull xx = pack2(ir[kw]);
          const ulonglong2* wq = (const ulonglong2*)(w2t + (ci * 25 + kh * 5 + kw) * 16);
          ulonglong2 q0 = wq[0], q1 = wq[1], q2 = wq[2], q3 = wq[3];
          ffma2(acc[0], xx, q0.x); ffma2(acc[1], xx, q0.y);
          ffma2(acc[2], xx, q1.x); ffma2(acc[3], xx, q1.y);
          ffma2(acc[4], xx, q2.x); ffma2(acc[5], xx, q2.y);
          ffma2(acc[6], xx, q3.x); ffma2(acc[7], xx, q3.y);
        }
      }
    }
    float* act11 = sm + OFF_ACT11;
    const float* sb2 = sm + OFF_SB2;
#pragma unroll
    for (int q = 0; q < 8; q++) {
      float2 v = unpack2(acc[q]);
      int co = 2 * q;
      act11[co * 121 + tid]       = lrelu(v.x + sb2[co]);
      act11[(co + 1) * 121 + tid] = lrelu(v.y + sb2[co + 1]);
    }
  }
  __syncthreads();

  // ---- phase 4: gaze11 in-place ----
  if (tid < 176) {
    int c = tid / 11, h = tid - c * 11;
    float* row = sm + OFF_ACT11 + c * 121 + h * 11;
    const float* K = sm + OFF_K11;
    float a[11];
#pragma unroll
    for (int w = 0; w < 11; w++) a[w] = row[w];
    ull acc[6];
#pragma unroll
    for (int q = 0; q < 6; q++) acc[q] = 0ULL;
#pragma unroll
    for (int w = 0; w < 11; w++) {
      ull xx = pack2(a[w]);
      const ulonglong2* kr = (const ulonglong2*)(K + w * 12);
#pragma unroll
      for (int q = 0; q < 3; q++) {
        ulonglong2 kv = kr[q];
        ffma2(acc[2 * q], xx, kv.x);
        ffma2(acc[2 * q + 1], xx, kv.y);
      }
    }
#pragma unroll
    for (int q = 0; q < 5; q++) {
      float2 v = unpack2(acc[q]);
      row[2 * q] = v.x; row[2 * q + 1] = v.y;
    }
    row[10] = unpack2(acc[5]).x;
  }
  __syncthreads();

  // ---- phase 5: conv3 3x3 16->16, leaky ----
  if (tid < 81) {
    int oh = tid / 9, ow = tid - oh * 9;
    ull acc[8];
#pragma unroll
    for (int q = 0; q < 8; q++) acc[q] = 0ULL;
    const float* w3t = sm + OFF_W3T;
    const float* act11 = sm + OFF_ACT11;
    for (int ci = 0; ci < 16; ci++) {
      const float* irow = act11 + ci * 121;
#pragma unroll
      for (int kh = 0; kh < 3; kh++) {
        const float* ir = irow + (oh + kh) * 11 + ow;
#pragma unroll
        for (int kw = 0; kw < 3; kw++) {
          ull xx = pack2(ir[kw]);
          const ulonglong2* wq = (const ulonglong2*)(w3t + (ci * 9 + kh * 3 + kw) * 16);
          ulonglong2 q0 = wq[0], q1 = wq[1], q2 = wq[2], q3 = wq[3];
          ffma2(acc[0], xx, q0.x); ffma2(acc[1], xx, q0.y);
          ffma2(acc[2], xx, q1.x); ffma2(acc[3], xx, q1.y);
          ffma2(acc[4], xx, q2.x); ffma2(acc[5], xx, q2.y);
          ffma2(acc[6], xx, q3.x); ffma2(acc[7], xx, q3.y);
        }
      }
    }
    float* act9 = sm + OFF_ACT9;
    const float* sb3 = sm + OFF_SB3;
#pragma unroll
    for (int q = 0; q < 8; q++) {
      float2 v = unpack2(acc[q]);
      int co = 2 * q;
      act9[co * 81 + tid]       = lrelu(v.x + sb3[co]);
      act9[(co + 1) * 81 + tid] = lrelu(v.y + sb3[co + 1]);
    }
  }
  __syncthreads();

  // ---- phase 6: conv4 3x3 16->16, leaky -> g_xf + cm ----
  if (tid < 49) {
    int oh = tid / 7, ow = tid - oh * 7;
    ull acc[8];
#pragma unroll
    for (int q = 0; q < 8; q++) acc[q] = 0ULL;
    const float* w4t = sm + OFF_W4T;
    const float* act9 = sm + OFF_ACT9;
    for (int ci = 0; ci < 16; ci++) {
      const float* irow = act9 + ci * 81;
#pragma unroll
      for (int kh = 0; kh < 3; kh++) {
        const float* ir = irow + (oh + kh) * 9 + ow;
#pragma unroll
        for (int kw = 0; kw < 3; kw++) {
          ull xx = pack2(ir[kw]);
          const ulonglong2* wq = (const ulonglong2*)(w4t + (ci * 9 + kh * 3 + kw) * 16);
          ulonglong2 q0 = wq[0], q1 = wq[1], q2 = wq[2], q3 = wq[3];
          ffma2(acc[0], xx, q0.x); ffma2(acc[1], xx, q0.y);
          ffma2(acc[2], xx, q1.x); ffma2(acc[3], xx, q1.y);
          ffma2(acc[4], xx, q2.x); ffma2(acc[5], xx, q2.y);
          ffma2(acc[6], xx, q3.x); ffma2(acc[7], xx, q3.y);
        }
      }
    }
    const float* sb4 = sm + OFF_SB4;
    float* xp = g_xf + (size_t)n * 784 + tid;
    float cs = 0.f;
#pragma unroll
    for (int q = 0; q < 8; q++) {
      float2 v = unpack2(acc[q]);
      int co = 2 * q;
      float v0 = lrelu(v.x + sb4[co]);
      float v1 = lrelu(v.y + sb4[co + 1]);
      xp[co * 49] = v0;
      xp[(co + 1) * 49] = v1;
      cs += v0 + v1;
    }
    g_cm[(size_t)n * 49 + tid] = cs;
  }
}

// ---------------- fc ----------------
__global__ __launch_bounds__(256) void k_fc(const float* __restrict__ w1,
                                            const float* __restrict__ b1,
                                            const float* __restrict__ w2,
                                            const float* __restrict__ b2) {
  __shared__ float As[64][17];
  __shared__ float Bs[16][68];
  __shared__ float prs[16][64];
  int tid = threadIdx.x;
  int s0 = blockIdx.x * 64;
  int sg = tid >> 4, jg = tid & 15;
  float acc[4][4];
#pragma unroll
  for (int i = 0; i < 4; i++)
#pragma unroll
    for (int u = 0; u < 4; u++) acc[i][u] = 0.f;
  for (int k0 = 0; k0 < 784; k0 += 16) {
    for (int i = tid; i < 1024; i += 256) {
      int s = i >> 4, kk = i & 15;
      As[s][kk] = g_xf[(size_t)(s0 + s) * 784 + k0 + kk];
    }
    for (int i = tid; i < 1024; i += 256) {
      int j = i >> 4, kk = i & 15;
      Bs[kk][j] = w1[j * 784 + k0 + kk];
    }
    __syncthreads();
#pragma unroll
    for (int kk = 0; kk < 16; kk++) {
      float av[4], bv[4];
#pragma unroll
      for (int i = 0; i < 4; i++) av[i] = As[sg * 4 + i][kk];
#pragma unroll
      for (int u = 0; u < 4; u++) bv[u] = Bs[kk][jg * 4 + u];
#pragma unroll
      for (int i = 0; i < 4; i++)
#pragma unroll
        for (int u = 0; u < 4; u++) acc[i][u] += av[i] * bv[u];
    }
    __syncthreads();
  }
#pragma unroll
  for (int i = 0; i < 4; i++) {
    float pr = 0.f;
#pragma unroll
    for (int u = 0; u < 4; u++) {
      int j = jg * 4 + u;
      float h = acc[i][u] + b1[j];
      h = lrelu(h);
      pr += h * w2[j];
    }
    prs[jg][sg * 4 + i] = pr;
  }
  __syncthreads();
  if (tid < 64) {
    float s = 0.f;
#pragma unroll
    for (int j = 0; j < 16; j++) s += prs[j][tid];
    g_r[s0 + tid] = s + b2[0];
  }
}

__global__ void k_reduce_r(float* __restrict__ out) {
  __shared__ float sab[64];
  int tid = threadIdx.x;
  int traj = tid >> 5, b = tid & 31;
  float s = 0.f, sa = 0.f;
  for (int t = 0; t < 64; t++) {
    float r = g_r[traj * 2048 + t * 32 + b];
    s += r;
    sa += fabsf(r);
  }
  out[tid] = s;
  sab[tid] = sa;
  __syncthreads();
  if (tid < 32) out[64 + tid] = sab[tid] + sab[32 + tid];
}

__global__ __launch_bounds__(256) void k_cmnorm(float* __restrict__ out) {
  __shared__ float sv[1568];
  __shared__ float smn[8], smx[8];
  __shared__ float fmn, fmx;
  int idx = blockIdx.x;
  int traj = idx >> 6, t = idx & 63;
  int tid = threadIdx.x;
  const float* base = g_cm + ((size_t)(traj * 2048 + t * 32)) * 49;
  float mn = 1e30f, mx = -1e30f;
  for (int i = tid; i < 1568; i += 256) {
    float v = base[i];
    sv[i] = v;
    mn = fminf(mn, v);
    mx = fmaxf(mx, v);
  }
#pragma unroll
  for (int o = 16; o; o >>= 1) {
    mn = fminf(mn, __shfl_xor_sync(0xffffffffu, mn, o));
    mx = fmaxf(mx, __shfl_xor_sync(0xffffffffu, mx, o));
  }
  if ((tid & 31) == 0) { smn[tid >> 5] = mn; smx[tid >> 5] = mx; }
  __syncthreads();
  if (tid == 0) {
    float a = smn[0], bb = smx[0];
    for (int i = 1; i < 8; i++) { a = fminf(a, smn[i]); bb = fmaxf(bb, smx[i]); }
    fmn = a; fmx = bb;
  }
  __syncthreads();
  float m = fmn, inv = 1.f / (fmx - m);
  float* o = out + 96 + (size_t)traj * 100352 + (size_t)t * 1568;
  for (int i = tid; i < 1568; i += 256) o[i] = (sv[i] - m) * inv;
}

extern "C" void kernel_launch(void* const* d_in, const int* in_sizes, int n_in,
                              void* d_out, int out_size) {
  const float* ti   = (const float*)d_in[0];
  const float* tj   = (const float*)d_in[1];
  const float* g26i = (const float*)d_in[2];
  const float* g11i = (const float*)d_in[3];
  const float* g26j = (const float*)d_in[4];
  const float* g11j = (const float*)d_in[5];
  const float* w1 = (const float*)d_in[6];  const float* b1 = (const float*)d_in[7];
  const float* w2 = (const float*)d_in[8];  const float* b2 = (const float*)d_in[9];
  const float* w3 = (const float*)d_in[10]; const float* b3 = (const float*)d_in[11];
  const float* w4 = (const float*)d_in[12]; const float* b4 = (const float*)d_in[13];
  const float* f1w = (const float*)d_in[14]; const float* f1b = (const float*)d_in[15];
  const float* f2w = (const float*)d_in[16]; const float* f2b = (const float*)d_in[17];
  float* out = (float*)d_out;

  cudaFuncSetAttribute(k_net, cudaFuncAttributeMaxDynamicSharedMemorySize,
                       SMEM_FLOATS * 4);

  k_net<<<NTOT, 256, SMEM_FLOATS * 4>>>(ti, tj, g26i, g26j, g11i, g11j,
                                        w1, b1, w2, b2, w3, b3, w4, b4);
  k_fc<<<NTOT / 64, 256>>>(f1w, f1b, f2w, f2b);
  k_reduce_r<<<1, 64>>>(out);
  k_cmnorm<<<128, 256>>>(out);
}

// round 5
// speedup vs baseline: 1.4754x; 1.0067x over previous
#include <cuda_runtime.h>
#include <math.h>

#define NPT 2048
#define NTOT 4096
typedef unsigned long long ull;

__device__ float g_xf[(size_t)NTOT * 784];
__device__ float g_cm[(size_t)NTOT * 49];
__device__ float g_r[NTOT];
// pre-transposed weights (written once per launch by k_prep)
__device__ float g_w1t[3136];
__device__ float g_w2t[6400];
__device__ float g_w3t[2304];
__device__ float g_w4t[2304];

__device__ __forceinline__ float lrelu(float v) { return v >= 0.f ? v : 0.01f * v; }
__device__ __forceinline__ ull pack2(float x) {
  ull r; asm("mov.b64 %0,{%1,%1};" : "=l"(r) : "f"(x)); return r;
}
__device__ __forceinline__ void ffma2(ull& d, ull a, ull b) {
  asm("fma.rn.f32x2 %0,%1,%2,%0;" : "+l"(d) : "l"(a), "l"(b));
}
__device__ __forceinline__ float2 unpack2(ull v) {
  float2 r; asm("mov.b64 {%0,%1},%2;" : "=f"(r.x), "=f"(r.y) : "l"(v)); return r;
}

// smem float offsets (total 26078 floats = 104312 B -> 2 blocks/SM)
#define OFF_ACT26 0        // 10816  [co*676 + p]
#define OFF_W2T   10816    // 6400   [(ci*25+t)*16 + co]
#define OFF_W3T   17216    // 2304
#define OFF_W4T   19520    // 2304
#define OFF_K26   21824    // 728    [w*28 + k]
#define OFF_K11   22552    // 132    [w*12 + k]
#define OFF_ACT11 22684    // 1936   [co*121 + p]   (aliases W1 region)
#define OFF_ACT9  24620    // 1296   [co*81 + p]
#define OFF_W1    22684    // 3136   [(kh*7+kw)*64 + ci*16 + co] (dead after conv1)
#define OFF_SB1   25916
#define OFF_SB2   25932
#define OFF_SB3   25948
#define OFF_SB4   25964
#define OFF_SCM   25980    // 98
#define SMEM_FLOATS 26078

// ---------------- one-time weight transpose ----------------
__global__ void k_prep(const float* __restrict__ w1, const float* __restrict__ w2,
                       const float* __restrict__ w3, const float* __restrict__ w4) {
  int tid = blockIdx.x * blockDim.x + threadIdx.x;
  for (int i = tid; i < 3136; i += 2048) {
    int co = i & 15, r = i >> 4, ci = r & 3, kk = r >> 2;
    g_w1t[i] = w1[co * 196 + ci * 49 + kk];
  }
  for (int i = tid; i < 6400; i += 2048) g_w2t[i] = w2[(i & 15) * 400 + (i >> 4)];
  for (int i = tid; i < 2304; i += 2048) g_w3t[i] = w3[(i & 15) * 144 + (i >> 4)];
  for (int i = tid; i < 2304; i += 2048) g_w4t[i] = w4[(i & 15) * 144 + (i >> 4)];
}

__global__ __launch_bounds__(256, 2) void k_net(
    const float* __restrict__ ti, const float* __restrict__ tj,
    const float* __restrict__ g26i, const float* __restrict__ g26j,
    const float* __restrict__ g11i, const float* __restrict__ g11j,
    const float* __restrict__ b1, const float* __restrict__ b2,
    const float* __restrict__ b3, const float* __restrict__ b4) {
  extern __shared__ float sm[];
  int n = blockIdx.x, tid = threadIdx.x;
  const float sc = 1.0f / (0.7f * 0.3f);

  const float* x   = (n < NPT) ? ti   + (size_t)n * 28224 : tj   + (size_t)(n - NPT) * 28224;
  const float* g26 = (n < NPT) ? g26i + (size_t)n * 676   : g26j + (size_t)(n - NPT) * 676;
  const float* g11 = (n < NPT) ? g11i + (size_t)n * 121   : g11j + (size_t)(n - NPT) * 121;

  // ---- phase 0: load weights (coalesced) / gaze kernels ----
  for (int i = tid; i < 3136; i += 256) sm[OFF_W1 + i] = g_w1t[i];
  for (int i = tid; i < 6400; i += 256) sm[OFF_W2T + i] = g_w2t[i];
  for (int i = tid; i < 2304; i += 256) sm[OFF_W3T + i] = g_w3t[i];
  for (int i = tid; i < 2304; i += 256) sm[OFF_W4T + i] = g_w4t[i];
  for (int i = tid; i < 728; i += 256) {
    int wdx = i / 28, k = i - wdx * 28;
    sm[OFF_K26 + i] = (k < 26) ? (g26[wdx * 26 + k] - 0.3f) * sc : 0.f;
  }
  for (int i = tid; i < 132; i += 256) {
    int wdx = i / 12, k = i - wdx * 12;
    sm[OFF_K11 + i] = (k < 11) ? (g11[wdx * 11 + k] - 0.3f) * sc : 0.f;
  }
  if (tid < 16) {
    sm[OFF_SB1 + tid] = b1[tid]; sm[OFF_SB2 + tid] = b2[tid];
    sm[OFF_SB3 + tid] = b3[tid]; sm[OFF_SB4 + tid] = b4[tid];
  }
  __syncthreads();

  // ---- phase 1: conv1 7x7 s3 4->16, leaky. Pixel-pairs, input from global ----
  {
    const float4* xg = (const float4*)x;
    const float* sw1 = sm + OFF_W1;
    const float* sb1 = sm + OFF_SB1;
    for (int i = tid; i < 338; i += 256) {
      int oh = i / 13, j = i - oh * 13;
      int ow0 = 2 * j;
      ull a0[8], a1[8];
#pragma unroll
      for (int q = 0; q < 8; q++) { a0[q] = 0ULL; a1[q] = 0ULL; }
      for (int kh = 0; kh < 7; kh++) {
        const float4* xr = xg + (oh * 3 + kh) * 84 + 6 * j;
        float4 xv[10];
#pragma unroll
        for (int q = 0; q < 10; q++) xv[q] = xr[q];
#pragma unroll
        for (int kw = 0; kw < 7; kw++) {
          const ulonglong2* wq = (const ulonglong2*)(sw1 + (kh * 7 + kw) * 64);
          float xa[4] = {xv[kw].x, xv[kw].y, xv[kw].z, xv[kw].w};
          float xb[4] = {xv[kw + 3].x, xv[kw + 3].y, xv[kw + 3].z, xv[kw + 3].w};
#pragma unroll
          for (int ci = 0; ci < 4; ci++) {
            ull xx0 = pack2(xa[ci]);
            ull xx1 = pack2(xb[ci]);
            ulonglong2 q0 = wq[ci * 4 + 0], q1 = wq[ci * 4 + 1];
            ulonglong2 q2 = wq[ci * 4 + 2], q3 = wq[ci * 4 + 3];
            ffma2(a0[0], xx0, q0.x); ffma2(a0[1], xx0, q0.y);
            ffma2(a0[2], xx0, q1.x); ffma2(a0[3], xx0, q1.y);
            ffma2(a0[4], xx0, q2.x); ffma2(a0[5], xx0, q2.y);
            ffma2(a0[6], xx0, q3.x); ffma2(a0[7], xx0, q3.y);
            ffma2(a1[0], xx1, q0.x); ffma2(a1[1], xx1, q0.y);
            ffma2(a1[2], xx1, q1.x); ffma2(a1[3], xx1, q1.y);
            ffma2(a1[4], xx1, q2.x); ffma2(a1[5], xx1, q2.y);
            ffma2(a1[6], xx1, q3.x); ffma2(a1[7], xx1, q3.y);
          }
        }
      }
      float* sact = sm + OFF_ACT26;
      int p0 = oh * 26 + ow0;
#pragma unroll
      for (int q = 0; q < 8; q++) {
        float2 v0 = unpack2(a0[q]);
        float2 v1 = unpack2(a1[q]);
        int co = 2 * q;
        sact[co * 676 + p0]           = lrelu(v0.x + sb1[co]);
        sact[(co + 1) * 676 + p0]     = lrelu(v0.y + sb1[co + 1]);
        sact[co * 676 + p0 + 1]       = lrelu(v1.x + sb1[co]);
        sact[(co + 1) * 676 + p0 + 1] = lrelu(v1.y + sb1[co + 1]);
      }
    }
  }
  __syncthreads();

  // ---- phase 2: gaze26 in-place (row per thread) ----
  for (int i = tid; i < 416; i += 256) {
    int c = i / 26, h = i - c * 26;
    float* row = sm + OFF_ACT26 + c * 676 + h * 26;
    const float* K = sm + OFF_K26;
    float a[26];
#pragma unroll
    for (int w = 0; w < 26; w++) a[w] = row[w];
    ull acc[14];
#pragma unroll
    for (int q = 0; q < 14; q++) acc[q] = 0ULL;
#pragma unroll
    for (int w = 0; w < 26; w++) {
      ull xx = pack2(a[w]);
      const ulonglong2* kr = (const ulonglong2*)(K + w * 28);
#pragma unroll
      for (int q = 0; q < 7; q++) {
        ulonglong2 kv = kr[q];
        ffma2(acc[2 * q], xx, kv.x);
        ffma2(acc[2 * q + 1], xx, kv.y);
      }
    }
#pragma unroll
    for (int q = 0; q < 13; q++) {
      float2 v = unpack2(acc[q]);
      row[2 * q] = v.x; row[2 * q + 1] = v.y;
    }
  }
  __syncthreads();

  // ---- phase 3: conv2 5x5 s2 16->16, leaky. px x co-half per thread (242) ----
  if (tid < 242) {
    int half = tid & 1, p = tid >> 1;
    int oh = p / 11, ow = p - oh * 11;
    int ih0 = oh * 2, iw0 = ow * 2;
    ull acc[4] = {0ULL, 0ULL, 0ULL, 0ULL};
    const float* w2t = sm + OFF_W2T;
    const float* sact = sm + OFF_ACT26;
    for (int ci = 0; ci < 16; ci++) {
      const float* irow = sact + ci * 676;
#pragma unroll
      for (int kh = 0; kh < 5; kh++) {
        const float* ir = irow + (ih0 + kh) * 26 + iw0;
#pragma unroll
        for (int kw = 0; kw < 5; kw++) {
          ull xx = pack2(ir[kw]);
          const ulonglong2* wq =
              (const ulonglong2*)(w2t + (ci * 25 + kh * 5 + kw) * 16 + half * 8);
          ulonglong2 q0 = wq[0], q1 = wq[1];
          ffma2(acc[0], xx, q0.x); ffma2(acc[1], xx, q0.y);
          ffma2(acc[2], xx, q1.x); ffma2(acc[3], xx, q1.y);
        }
      }
    }
    float* act11 = sm + OFF_ACT11;
    const float* sb2 = sm + OFF_SB2;
#pragma unroll
    for (int q = 0; q < 4; q++) {
      float2 v = unpack2(acc[q]);
      int co = half * 8 + 2 * q;
      act11[co * 121 + p]       = lrelu(v.x + sb2[co]);
      act11[(co + 1) * 121 + p] = lrelu(v.y + sb2[co + 1]);
    }
  }
  __syncthreads();

  // ---- phase 4: gaze11 in-place (176) ----
  if (tid < 176) {
    int c = tid / 11, h = tid - c * 11;
    float* row = sm + OFF_ACT11 + c * 121 + h * 11;
    const float* K = sm + OFF_K11;
    float a[11];
#pragma unroll
    for (int w = 0; w < 11; w++) a[w] = row[w];
    ull acc[6];
#pragma unroll
    for (int q = 0; q < 6; q++) acc[q] = 0ULL;
#pragma unroll
    for (int w = 0; w < 11; w++) {
      ull xx = pack2(a[w]);
      const ulonglong2* kr = (const ulonglong2*)(K + w * 12);
#pragma unroll
      for (int q = 0; q < 3; q++) {
        ulonglong2 kv = kr[q];
        ffma2(acc[2 * q], xx, kv.x);
        ffma2(acc[2 * q + 1], xx, kv.y);
      }
    }
#pragma unroll
    for (int q = 0; q < 5; q++) {
      float2 v = unpack2(acc[q]);
      row[2 * q] = v.x; row[2 * q + 1] = v.y;
    }
    row[10] = unpack2(acc[5]).x;
  }
  __syncthreads();

  // ---- phase 5: conv3 3x3 16->16, leaky. px x co-half (162) ----
  if (tid < 162) {
    int half = tid & 1, p = tid >> 1;
    int oh = p / 9, ow = p - oh * 9;
    ull acc[4] = {0ULL, 0ULL, 0ULL, 0ULL};
    const float* w3t = sm + OFF_W3T;
    const float* act11 = sm + OFF_ACT11;
    for (int ci = 0; ci < 16; ci++) {
      const float* irow = act11 + ci * 121;
#pragma unroll
      for (int kh = 0; kh < 3; kh++) {
        const float* ir = irow + (oh + kh) * 11 + ow;
#pragma unroll
        for (int kw = 0; kw < 3; kw++) {
          ull xx = pack2(ir[kw]);
          const ulonglong2* wq =
              (const ulonglong2*)(w3t + (ci * 9 + kh * 3 + kw) * 16 + half * 8);
          ulonglong2 q0 = wq[0], q1 = wq[1];
          ffma2(acc[0], xx, q0.x); ffma2(acc[1], xx, q0.y);
          ffma2(acc[2], xx, q1.x); ffma2(acc[3], xx, q1.y);
        }
      }
    }
    float* act9 = sm + OFF_ACT9;
    const float* sb3 = sm + OFF_SB3;
#pragma unroll
    for (int q = 0; q < 4; q++) {
      float2 v = unpack2(acc[q]);
      int co = half * 8 + 2 * q;
      act9[co * 81 + p]       = lrelu(v.x + sb3[co]);
      act9[(co + 1) * 81 + p] = lrelu(v.y + sb3[co + 1]);
    }
  }
  __syncthreads();

  // ---- phase 6: conv4 3x3 16->16, leaky -> g_xf + cm. px x co-half (98) ----
  if (tid < 98) {
    int half = tid & 1, p = tid >> 1;
    int oh = p / 7, ow = p - oh * 7;
    ull acc[4] = {0ULL, 0ULL, 0ULL, 0ULL};
    const float* w4t = sm + OFF_W4T;
    const float* act9 = sm + OFF_ACT9;
    for (int ci = 0; ci < 16; ci++) {
      const float* irow = act9 + ci * 81;
#pragma unroll
      for (int kh = 0; kh < 3; kh++) {
        const float* ir = irow + (oh + kh) * 9 + ow;
#pragma unroll
        for (int kw = 0; kw < 3; kw++) {
          ull xx = pack2(ir[kw]);
          const ulonglong2* wq =
              (const ulonglong2*)(w4t + (ci * 9 + kh * 3 + kw) * 16 + half * 8);
          ulonglong2 q0 = wq[0], q1 = wq[1];
          ffma2(acc[0], xx, q0.x); ffma2(acc[1], xx, q0.y);
          ffma2(acc[2], xx, q1.x); ffma2(acc[3], xx, q1.y);
        }
      }
    }
    const float* sb4 = sm + OFF_SB4;
    float* xp = g_xf + (size_t)n * 784 + p;
    float cs = 0.f;
#pragma unroll
    for (int q = 0; q < 4; q++) {
      float2 v = unpack2(acc[q]);
      int co = half * 8 + 2 * q;
      float v0 = lrelu(v.x + sb4[co]);
      float v1 = lrelu(v.y + sb4[co + 1]);
      xp[co * 49] = v0;
      xp[(co + 1) * 49] = v1;
      cs += v0 + v1;
    }
    sm[OFF_SCM + tid] = cs;
  }
  __syncthreads();
  if (tid < 49)
    g_cm[(size_t)n * 49 + tid] = sm[OFF_SCM + 2 * tid] + sm[OFF_SCM + 2 * tid + 1];
}

// ---------------- fc ----------------
__global__ __launch_bounds__(256) void k_fc(const float* __restrict__ w1,
                                            const float* __restrict__ b1,
                                            const float* __restrict__ w2,
                                            const float* __restrict__ b2) {
  __shared__ float As[64][17];
  __shared__ float Bs[16][68];
  __shared__ float prs[16][64];
  int tid = threadIdx.x;
  int s0 = blockIdx.x * 64;
  int sg = tid >> 4, jg = tid & 15;
  float acc[4][4];
#pragma unroll
  for (int i = 0; i < 4; i++)
#pragma unroll
    for (int u = 0; u < 4; u++) acc[i][u] = 0.f;
  for (int k0 = 0; k0 < 784; k0 += 16) {
    for (int i = tid; i < 1024; i += 256) {
      int s = i >> 4, kk = i & 15;
      As[s][kk] = g_xf[(size_t)(s0 + s) * 784 + k0 + kk];
    }
    for (int i = tid; i < 1024; i += 256) {
      int j = i >> 4, kk = i & 15;
      Bs[kk][j] = w1[j * 784 + k0 + kk];
    }
    __syncthreads();
#pragma unroll
    for (int kk = 0; kk < 16; kk++) {
      float av[4], bv[4];
#pragma unroll
      for (int i = 0; i < 4; i++) av[i] = As[sg * 4 + i][kk];
#pragma unroll
      for (int u = 0; u < 4; u++) bv[u] = Bs[kk][jg * 4 + u];
#pragma unroll
      for (int i = 0; i < 4; i++)
#pragma unroll
        for (int u = 0; u < 4; u++) acc[i][u] += av[i] * bv[u];
    }
    __syncthreads();
  }
#pragma unroll
  for (int i = 0; i < 4; i++) {
    float pr = 0.f;
#pragma unroll
    for (int u = 0; u < 4; u++) {
      int j = jg * 4 + u;
      float h = acc[i][u] + b1[j];
      h = lrelu(h);
      pr += h * w2[j];
    }
    prs[jg][sg * 4 + i] = pr;
  }
  __syncthreads();
  if (tid < 64) {
    float s = 0.f;
#pragma unroll
    for (int j = 0; j < 16; j++) s += prs[j][tid];
    g_r[s0 + tid] = s + b2[0];
  }
}

__global__ void k_reduce_r(float* __restrict__ out) {
  __shared__ float sab[64];
  int tid = threadIdx.x;
  int traj = tid >> 5, b = tid & 31;
  float s = 0.f, sa = 0.f;
  for (int t = 0; t < 64; t++) {
    float r = g_r[traj * 2048 + t * 32 + b];
    s += r;
    sa += fabsf(r);
  }
  out[tid] = s;
  sab[tid] = sa;
  __syncthreads();
  if (tid < 32) out[64 + tid] = sab[tid] + sab[32 + tid];
}

__global__ __launch_bounds__(256) void k_cmnorm(float* __restrict__ out) {
  __shared__ float sv[1568];
  __shared__ float smn[8], smx[8];
  __shared__ float fmn, fmx;
  int idx = blockIdx.x;
  int traj = idx >> 6, t = idx & 63;
  int tid = threadIdx.x;
  const float* base = g_cm + ((size_t)(traj * 2048 + t * 32)) * 49;
  float mn = 1e30f, mx = -1e30f;
  for (int i = tid; i < 1568; i += 256) {
    float v = base[i];
    sv[i] = v;
    mn = fminf(mn, v);
    mx = fmaxf(mx, v);
  }
#pragma unroll
  for (int o = 16; o; o >>= 1) {
    mn = fminf(mn, __shfl_xor_sync(0xffffffffu, mn, o));
    mx = fmaxf(mx, __shfl_xor_sync(0xffffffffu, mx, o));
  }
  if ((tid & 31) == 0) { smn[tid >> 5] = mn; smx[tid >> 5] = mx; }
  __syncthreads();
  if (tid == 0) {
    float a = smn[0], bb = smx[0];
    for (int i = 1; i < 8; i++) { a = fminf(a, smn[i]); bb = fmaxf(bb, smx[i]); }
    fmn = a; fmx = bb;
  }
  __syncthreads();
  float m = fmn, inv = 1.f / (fmx - m);
  float* o = out + 96 + (size_t)traj * 100352 + (size_t)t * 1568;
  for (int i = tid; i < 1568; i += 256) o[i] = (sv[i] - m) * inv;
}

extern "C" void kernel_launch(void* const* d_in, const int* in_sizes, int n_in,
                              void* d_out, int out_size) {
  const float* ti   = (const float*)d_in[0];
  const float* tj   = (const float*)d_in[1];
  const float* g26i = (const float*)d_in[2];
  const float* g11i = (const float*)d_in[3];
  const float* g26j = (const float*)d_in[4];
  const float* g11j = (const float*)d_in[5];
  const float* w1 = (const float*)d_in[6];  const float* b1 = (const float*)d_in[7];
  const float* w2 = (const float*)d_in[8];  const float* b2 = (const float*)d_in[9];
  const float* w3 = (const float*)d_in[10]; const float* b3 = (const float*)d_in[11];
  const float* w4 = (const float*)d_in[12]; const float* b4 = (const float*)d_in[13];
  const float* f1w = (const float*)d_in[14]; const float* f1b = (const float*)d_in[15];
  const float* f2w = (const float*)d_in[16]; const float* f2b = (const float*)d_in[17];
  float* out = (float*)d_out;

  cudaFuncSetAttribute(k_net, cudaFuncAttributeMaxDynamicSharedMemorySize,
                       SMEM_FLOATS * 4);

  k_prep<<<4, 512>>>(w1, w2, w3, w4);
  k_net<<<NTOT, 256, SMEM_FLOATS * 4>>>(ti, tj, g26i, g26j, g11i, g11j,
                                        b1, b2, b3, b4);
  k_fc<<<NTOT / 64, 256>>>(f1w, f1b, f2w, f2b);
  k_reduce_r<<<1, 64>>>(out);
  k_cmnorm<<<128, 256>>>(out);
}